// round 6
// baseline (speedup 1.0000x reference)
#include <cuda_runtime.h>
#include <cuda_bf16.h>
#include <math.h>

// CannyFilter B=32,C=3,H=W=512 — unified warp-per-row path, tile 64x16.
// Stages: channel-sum load -> blur(3x3) -> sobel-mag -> D(3x3) -> R(3x3).
// One warp processes full-width rows => all shared accesses are consecutive
// bytes of one row => bank-conflict free. Boundary handled by warp-uniform
// y-masks + per-lane x-mask multiplies (exact zero-pad semantics everywhere).

#define IMG 512
#define TSX 64
#define TSY 16
#define STRIDE 72          // smem row stride (floats); 288B, 16B aligned
#define SROWS 24

// cW: [0:9) G, [9:18) X, [18:27) Y, [27:36) D(sum of 8), [36:45) R
__constant__ float cW[45];
__device__ float g_wbuf[45];

__global__ void prep_weights(const float* __restrict__ g, const float* __restrict__ sx,
                             const float* __restrict__ sy, const float* __restrict__ dw,
                             const float* __restrict__ nw)
{
    int t = threadIdx.x;
    if (t < 9) {
        g_wbuf[t]      = g[t];
        g_wbuf[9 + t]  = sx[t];
        g_wbuf[18 + t] = sy[t];
        float d = 0.f;
        for (int k = 0; k < 8; k++) d += dw[k * 9 + t];
        g_wbuf[27 + t] = d;
        g_wbuf[36 + t] = nw[t];
    }
}

__global__ __launch_bounds__(256)
void canny_main(const float* __restrict__ img, float* __restrict__ out)
{
    __shared__ __align__(16) float sI[SROWS * STRIDE];   // img tile; later reused as S
    __shared__ __align__(16) float sB[SROWS * STRIDE];   // blur
    __shared__ __align__(16) float sM[SROWS * STRIDE];   // magnitude

    const int tid  = threadIdx.x;
    const int lane = tid & 31;
    const int wrp  = tid >> 5;
    const int X0 = blockIdx.x * TSX, Y0 = blockIdx.y * TSY, b = blockIdx.z;
    const float* im = img + (size_t)b * 3 * IMG * IMG;
    float* ob = out + (size_t)b * IMG * IMG;

    // ---------- stage 0: 24x72 channel-summed img tile (float4, masked) ----------
    {
        float4* sI4 = (float4*)sI;
        // 432 float4 slots, 256 threads: thread t handles slots t and t+256.
        #pragma unroll
        for (int it = 0; it < 2; it++) {
            const int i = tid + it * 256;
            if (i < 24 * 18) {
                const int r = (it == 0) ? (tid / 18) : ((tid + 256) / 18);
                const int c4 = i - r * 18;
                const int gy = Y0 - 4 + r;
                const int gx = X0 - 4 + c4 * 4;
                float4 s = make_float4(0.f, 0.f, 0.f, 0.f);
                if ((unsigned)gy < IMG && (unsigned)gx < IMG) {
                    const float4* p = (const float4*)(im + gy * IMG + gx);
                    const float4 a = __ldg(p);
                    const float4 c = __ldg(p + IMG * IMG / 4);
                    const float4 d = __ldg(p + 2 * IMG * IMG / 4);
                    s = make_float4(a.x + c.x + d.x, a.y + c.y + d.y,
                                    a.z + c.z + d.z, a.w + c.w + d.w);
                }
                sI4[r * 18 + c4] = s;
            }
        }
    }
    __syncthreads();

    // ---------- stage 1: blur (rows 0..21 valid, cols 0..69), k=3 strips ----------
    {
        const int r0 = wrp * 3;
        const int c0 = lane * 2, ct = 64 + lane * 2;
        const bool tl = lane < 3;
        float a0[3][2] = {{0,0},{0,0},{0,0}};
        float t0[3][2] = {{0,0},{0,0},{0,0}};
        #pragma unroll
        for (int ir = 0; ir < 5; ir++) {
            const int rr = (r0 + ir < SROWS) ? r0 + ir : SROWS - 1;
            const float* row = sI + rr * STRIDE;
            const float2 v = *(const float2*)(row + c0);
            const float2 u = *(const float2*)(row + c0 + 2);
            float2 vt = make_float2(0,0), ut = make_float2(0,0);
            if (tl) { vt = *(const float2*)(row + ct); ut = *(const float2*)(row + ct + 2); }
            #pragma unroll
            for (int k = 0; k < 3; k++) {
                const int ky = ir - k;
                if (ky >= 0 && ky < 3) {
                    const float g0 = cW[ky*3], g1 = cW[ky*3+1], g2 = cW[ky*3+2];
                    a0[k][0] = fmaf(g0, v.x, fmaf(g1, v.y, fmaf(g2, u.x, a0[k][0])));
                    a0[k][1] = fmaf(g0, v.y, fmaf(g1, u.x, fmaf(g2, u.y, a0[k][1])));
                    t0[k][0] = fmaf(g0, vt.x, fmaf(g1, vt.y, fmaf(g2, ut.x, t0[k][0])));
                    t0[k][1] = fmaf(g0, vt.y, fmaf(g1, ut.x, fmaf(g2, ut.y, t0[k][1])));
                }
            }
        }
        const float x0 = ((unsigned)(X0 - 3 + c0)     < IMG) ? 1.f : 0.f;
        const float x1 = ((unsigned)(X0 - 3 + c0 + 1) < IMG) ? 1.f : 0.f;
        const float xt0 = ((unsigned)(X0 - 3 + ct)     < IMG) ? 1.f : 0.f;
        const float xt1 = ((unsigned)(X0 - 3 + ct + 1) < IMG) ? 1.f : 0.f;
        #pragma unroll
        for (int k = 0; k < 3; k++) {
            const int r = r0 + k;
            if (r < SROWS) {
                const float ym = ((unsigned)(Y0 - 3 + r) < IMG) ? 1.f : 0.f;
                *(float2*)&sB[r * STRIDE + c0] =
                    make_float2(a0[k][0] * (x0 * ym), a0[k][1] * (x1 * ym));
                if (tl)
                    *(float2*)&sB[r * STRIDE + ct] =
                        make_float2(t0[k][0] * (xt0 * ym), t0[k][1] * (xt1 * ym));
            }
        }
    }
    __syncthreads();

    // ---------- stage 2: sobel magnitude (rows 0..19, cols 0..67), k=3 ----------
    {
        const int r0 = wrp * 3;
        const int c0 = lane * 2, ct = 64 + lane * 2;
        const bool tl = lane < 2;
        float ax[3][2] = {{0,0},{0,0},{0,0}}, ay[3][2] = {{0,0},{0,0},{0,0}};
        float bx2[3][2] = {{0,0},{0,0},{0,0}}, by2[3][2] = {{0,0},{0,0},{0,0}};
        #pragma unroll
        for (int ir = 0; ir < 5; ir++) {
            const int rr = (r0 + ir < SROWS) ? r0 + ir : SROWS - 1;
            const float* row = sB + rr * STRIDE;
            const float2 v = *(const float2*)(row + c0);
            const float2 u = *(const float2*)(row + c0 + 2);
            float2 vt = make_float2(0,0), ut = make_float2(0,0);
            if (tl) { vt = *(const float2*)(row + ct); ut = *(const float2*)(row + ct + 2); }
            #pragma unroll
            for (int k = 0; k < 3; k++) {
                const int ky = ir - k;
                if (ky >= 0 && ky < 3) {
                    const float sx0 = cW[9+ky*3], sx1 = cW[10+ky*3], sx2 = cW[11+ky*3];
                    const float sy0 = cW[18+ky*3], sy1 = cW[19+ky*3], sy2 = cW[20+ky*3];
                    ax[k][0] = fmaf(sx0, v.x, fmaf(sx1, v.y, fmaf(sx2, u.x, ax[k][0])));
                    ax[k][1] = fmaf(sx0, v.y, fmaf(sx1, u.x, fmaf(sx2, u.y, ax[k][1])));
                    ay[k][0] = fmaf(sy0, v.x, fmaf(sy1, v.y, fmaf(sy2, u.x, ay[k][0])));
                    ay[k][1] = fmaf(sy0, v.y, fmaf(sy1, u.x, fmaf(sy2, u.y, ay[k][1])));
                    bx2[k][0] = fmaf(sx0, vt.x, fmaf(sx1, vt.y, fmaf(sx2, ut.x, bx2[k][0])));
                    bx2[k][1] = fmaf(sx0, vt.y, fmaf(sx1, ut.x, fmaf(sx2, ut.y, bx2[k][1])));
                    by2[k][0] = fmaf(sy0, vt.x, fmaf(sy1, vt.y, fmaf(sy2, ut.x, by2[k][0])));
                    by2[k][1] = fmaf(sy0, vt.y, fmaf(sy1, ut.x, fmaf(sy2, ut.y, by2[k][1])));
                }
            }
        }
        const float x0 = ((unsigned)(X0 - 2 + c0)     < IMG) ? 1.f : 0.f;
        const float x1 = ((unsigned)(X0 - 2 + c0 + 1) < IMG) ? 1.f : 0.f;
        const float xt0 = ((unsigned)(X0 - 2 + ct)     < IMG) ? 1.f : 0.f;
        const float xt1 = ((unsigned)(X0 - 2 + ct + 1) < IMG) ? 1.f : 0.f;
        #pragma unroll
        for (int k = 0; k < 3; k++) {
            const int r = r0 + k;
            if (r < SROWS) {
                const float ym = ((unsigned)(Y0 - 2 + r) < IMG) ? 1.f : 0.f;
                const float m0 = sqrtf(ax[k][0]*ax[k][0] + ay[k][0]*ay[k][0]) * (1.f/3.f);
                const float m1 = sqrtf(ax[k][1]*ax[k][1] + ay[k][1]*ay[k][1]) * (1.f/3.f);
                *(float2*)&sM[r * STRIDE + c0] = make_float2(m0*(x0*ym), m1*(x1*ym));
                if (tl) {
                    const float n0 = sqrtf(bx2[k][0]*bx2[k][0] + by2[k][0]*by2[k][0]) * (1.f/3.f);
                    const float n1 = sqrtf(bx2[k][1]*bx2[k][1] + by2[k][1]*by2[k][1]) * (1.f/3.f);
                    *(float2*)&sM[r * STRIDE + ct] = make_float2(n0*(xt0*ym), n1*(xt1*ym));
                }
            }
        }
    }
    __syncthreads();

    // ---------- stage 3: S = conv(mag, D) into sI (rows 0..17, cols 0..65), k=3 ----------
    {
        const int r0 = wrp * 3;
        const int c0 = lane * 2, ct = 64 + lane * 2;
        const bool tl = lane < 1;
        float a0[3][2] = {{0,0},{0,0},{0,0}};
        float t0[3][2] = {{0,0},{0,0},{0,0}};
        #pragma unroll
        for (int ir = 0; ir < 5; ir++) {
            const int rr = (r0 + ir < SROWS) ? r0 + ir : SROWS - 1;
            const float* row = sM + rr * STRIDE;
            const float2 v = *(const float2*)(row + c0);
            const float2 u = *(const float2*)(row + c0 + 2);
            float2 vt = make_float2(0,0), ut = make_float2(0,0);
            if (tl) { vt = *(const float2*)(row + ct); ut = *(const float2*)(row + ct + 2); }
            #pragma unroll
            for (int k = 0; k < 3; k++) {
                const int ky = ir - k;
                if (ky >= 0 && ky < 3) {
                    const float d0 = cW[27+ky*3], d1 = cW[28+ky*3], d2 = cW[29+ky*3];
                    a0[k][0] = fmaf(d0, v.x, fmaf(d1, v.y, fmaf(d2, u.x, a0[k][0])));
                    a0[k][1] = fmaf(d0, v.y, fmaf(d1, u.x, fmaf(d2, u.y, a0[k][1])));
                    t0[k][0] = fmaf(d0, vt.x, fmaf(d1, vt.y, fmaf(d2, ut.x, t0[k][0])));
                    t0[k][1] = fmaf(d0, vt.y, fmaf(d1, ut.x, fmaf(d2, ut.y, t0[k][1])));
                }
            }
        }
        const float x0 = ((unsigned)(X0 - 1 + c0)     < IMG) ? 1.f : 0.f;
        const float x1 = ((unsigned)(X0 - 1 + c0 + 1) < IMG) ? 1.f : 0.f;
        const float xt0 = ((unsigned)(X0 - 1 + ct)     < IMG) ? 1.f : 0.f;
        const float xt1 = ((unsigned)(X0 - 1 + ct + 1) < IMG) ? 1.f : 0.f;
        __syncthreads();   // all threads: sM fully consumed before overwriting sI
        #pragma unroll
        for (int k = 0; k < 3; k++) {
            const int r = r0 + k;
            if (r < SROWS) {
                const float ym = ((unsigned)(Y0 - 1 + r) < IMG) ? 1.f : 0.f;
                *(float2*)&sI[r * STRIDE + c0] =
                    make_float2(a0[k][0] * (x0 * ym), a0[k][1] * (x1 * ym));
                if (tl)
                    *(float2*)&sI[r * STRIDE + ct] =
                        make_float2(t0[k][0] * (xt0 * ym), t0[k][1] * (xt1 * ym));
            }
        }
    }
    __syncthreads();

    // ---------- stage 4: out = conv(S, R), 64x16, k=2, no masks needed ----------
    {
        const int r0 = wrp * 2;
        const int c0 = lane * 2;
        float a0[2][2] = {{0,0},{0,0}};
        #pragma unroll
        for (int ir = 0; ir < 4; ir++) {
            const float* row = sI + (r0 + ir) * STRIDE;
            const float2 v = *(const float2*)(row + c0);
            const float2 u = *(const float2*)(row + c0 + 2);
            #pragma unroll
            for (int k = 0; k < 2; k++) {
                const int ky = ir - k;
                if (ky >= 0 && ky < 3) {
                    const float r0w = cW[36+ky*3], r1w = cW[37+ky*3], r2w = cW[38+ky*3];
                    a0[k][0] = fmaf(r0w, v.x, fmaf(r1w, v.y, fmaf(r2w, u.x, a0[k][0])));
                    a0[k][1] = fmaf(r0w, v.y, fmaf(r1w, u.x, fmaf(r2w, u.y, a0[k][1])));
                }
            }
        }
        #pragma unroll
        for (int k = 0; k < 2; k++)
            *(float2*)&ob[(Y0 + r0 + k) * IMG + X0 + c0] = make_float2(a0[k][0], a0[k][1]);
    }
}

extern "C" void kernel_launch(void* const* d_in, const int* in_sizes, int n_in,
                              void* d_out, int out_size)
{
    const float* img     = (const float*)d_in[0];
    const float* gauss_w = (const float*)d_in[1];
    const float* sobx_w  = (const float*)d_in[2];
    const float* soby_w  = (const float*)d_in[3];
    const float* dir_w   = (const float*)d_in[4];
    const float* nms_w   = (const float*)d_in[5];
    float* out = (float*)d_out;

    prep_weights<<<1, 32>>>(gauss_w, sobx_w, soby_w, dir_w, nms_w);

    void* wptr = nullptr;
    cudaGetSymbolAddress(&wptr, g_wbuf);
    cudaMemcpyToSymbolAsync(cW, wptr, 45 * sizeof(float), 0,
                            cudaMemcpyDeviceToDevice, 0);

    dim3 grid(IMG / TSX, IMG / TSY, 32);
    canny_main<<<grid, 256>>>(img, out);
}

// round 7
// speedup vs baseline: 1.4314x; 1.4314x over previous
#include <cuda_runtime.h>
#include <cuda_bf16.h>
#include <math.h>

// CannyFilter B=32,C=3,H=W=512 — unified masked 5-stage path, tile 64x32,
// 512 threads. Stages: channel-sum load -> blur -> sobel-mag -> D -> R.
// Flat 2col x krow thread maps (dense half-warp smem phases, ~conflict-free),
// 0/1-multiply boundary masks reproduce exact zero-pad semantics everywhere.

#define IMG 512
#define TSX 64
#define TSY 32
#define STRIDE 72      // smem row stride in floats (288B, 16B aligned)
#define SROWS 40

// cW: [0:9) G, [9:18) X, [18:27) Y, [27:36) D(sum of 8 dir), [36:45) R
__constant__ float cW[45];
__device__ float g_wbuf[45];

__global__ void prep_weights(const float* __restrict__ g, const float* __restrict__ sx,
                             const float* __restrict__ sy, const float* __restrict__ dw,
                             const float* __restrict__ nw)
{
    int t = threadIdx.x;
    if (t < 9) {
        g_wbuf[t]      = g[t];
        g_wbuf[9 + t]  = sx[t];
        g_wbuf[18 + t] = sy[t];
        float d = 0.f;
        for (int k = 0; k < 8; k++) d += dw[k * 9 + t];
        g_wbuf[27 + t] = d;
        g_wbuf[36 + t] = nw[t];
    }
}

__global__ __launch_bounds__(512, 3)
void canny_main(const float* __restrict__ img, float* __restrict__ out)
{
    __shared__ __align__(16) float sI[SROWS * STRIDE];   // img tile; reused for S
    __shared__ __align__(16) float sB[SROWS * STRIDE];   // blur (rows 0..37, cols 0..69)
    __shared__ __align__(16) float sM[SROWS * STRIDE];   // mag  (rows 0..35, cols 0..67)

    const int tid = threadIdx.x;
    const int X0 = blockIdx.x * TSX, Y0 = blockIdx.y * TSY, b = blockIdx.z;
    const float* im = img + (size_t)b * 3 * IMG * IMG;
    float* ob = out + (size_t)b * IMG * IMG;

    // ---------- stage 0: 40x72 channel-summed img tile (float4, masked) ----------
    {
        float4* sI4 = (float4*)sI;
        #pragma unroll
        for (int it = 0; it < 2; it++) {
            const int i = tid + it * 512;
            if (i < 40 * 18) {
                const int r = i / 18, c4 = i - r * 18;
                const int gy = Y0 - 4 + r;
                const int gx = X0 - 4 + c4 * 4;          // 16B aligned
                float4 s = make_float4(0.f, 0.f, 0.f, 0.f);
                if ((unsigned)gy < IMG && (unsigned)gx < IMG) {
                    const float4* p = (const float4*)(im + gy * IMG + gx);
                    const float4 a = __ldg(p);
                    const float4 c = __ldg(p + IMG * IMG / 4);
                    const float4 d = __ldg(p + 2 * IMG * IMG / 4);
                    s = make_float4(a.x + c.x + d.x, a.y + c.y + d.y,
                                    a.z + c.z + d.z, a.w + c.w + d.w);
                }
                sI4[r * 18 + c4] = s;
            }
        }
    }
    __syncthreads();

    // ---------- stage 1: blur, 70 cols x 38 rows, 2c x 3r, 455 threads ----------
    if (tid < 455) {
        const int rg = tid / 35, cg = tid - rg * 35;
        const int c0 = cg * 2, r0 = rg * 3;
        float acc[3][2] = {{0,0},{0,0},{0,0}};
        #pragma unroll
        for (int ir = 0; ir < 5; ir++) {
            const int rr = (r0 + ir < SROWS) ? r0 + ir : SROWS - 1;
            const float2 v = *(const float2*)&sI[rr * STRIDE + c0];
            const float2 u = *(const float2*)&sI[rr * STRIDE + c0 + 2];
            #pragma unroll
            for (int k = 0; k < 3; k++) {
                const int ky = ir - k;
                if (ky >= 0 && ky < 3) {
                    const float g0 = cW[ky*3], g1 = cW[ky*3+1], g2 = cW[ky*3+2];
                    acc[k][0] = fmaf(g0, v.x, fmaf(g1, v.y, fmaf(g2, u.x, acc[k][0])));
                    acc[k][1] = fmaf(g0, v.y, fmaf(g1, u.x, fmaf(g2, u.y, acc[k][1])));
                }
            }
        }
        const float x0 = ((unsigned)(X0 - 3 + c0)     < IMG) ? 1.f : 0.f;
        const float x1 = ((unsigned)(X0 - 3 + c0 + 1) < IMG) ? 1.f : 0.f;
        #pragma unroll
        for (int k = 0; k < 3; k++) {
            const int r = r0 + k;
            if (r < 38) {
                const float ym = ((unsigned)(Y0 - 3 + r) < IMG) ? 1.f : 0.f;
                *(float2*)&sB[r * STRIDE + c0] =
                    make_float2(acc[k][0] * (x0 * ym), acc[k][1] * (x1 * ym));
            }
        }
    }
    __syncthreads();

    // ---------- stage 2: sobel-mag, 68 cols x 36 rows, 2c x 3r, 408 threads ----------
    if (tid < 408) {
        const int rg = tid / 34, cg = tid - rg * 34;
        const int c0 = cg * 2, r0 = rg * 3;
        float ax[3][2] = {{0,0},{0,0},{0,0}}, ay[3][2] = {{0,0},{0,0},{0,0}};
        #pragma unroll
        for (int ir = 0; ir < 5; ir++) {
            const float2 v = *(const float2*)&sB[(r0 + ir) * STRIDE + c0];
            const float2 u = *(const float2*)&sB[(r0 + ir) * STRIDE + c0 + 2];
            #pragma unroll
            for (int k = 0; k < 3; k++) {
                const int ky = ir - k;
                if (ky >= 0 && ky < 3) {
                    const float sx0 = cW[9+ky*3], sx1 = cW[10+ky*3], sx2 = cW[11+ky*3];
                    const float sy0 = cW[18+ky*3], sy1 = cW[19+ky*3], sy2 = cW[20+ky*3];
                    ax[k][0] = fmaf(sx0, v.x, fmaf(sx1, v.y, fmaf(sx2, u.x, ax[k][0])));
                    ax[k][1] = fmaf(sx0, v.y, fmaf(sx1, u.x, fmaf(sx2, u.y, ax[k][1])));
                    ay[k][0] = fmaf(sy0, v.x, fmaf(sy1, v.y, fmaf(sy2, u.x, ay[k][0])));
                    ay[k][1] = fmaf(sy0, v.y, fmaf(sy1, u.x, fmaf(sy2, u.y, ay[k][1])));
                }
            }
        }
        const float x0 = ((unsigned)(X0 - 2 + c0)     < IMG) ? 1.f : 0.f;
        const float x1 = ((unsigned)(X0 - 2 + c0 + 1) < IMG) ? 1.f : 0.f;
        #pragma unroll
        for (int k = 0; k < 3; k++) {
            const int r = r0 + k;
            const float ym = ((unsigned)(Y0 - 2 + r) < IMG) ? 1.f : 0.f;
            const float m0 = sqrtf(ax[k][0]*ax[k][0] + ay[k][0]*ay[k][0]) * (1.f/3.f);
            const float m1 = sqrtf(ax[k][1]*ax[k][1] + ay[k][1]*ay[k][1]) * (1.f/3.f);
            *(float2*)&sM[r * STRIDE + c0] = make_float2(m0 * (x0 * ym), m1 * (x1 * ym));
        }
    }
    __syncthreads();

    // ---------- stage 3: S = conv(mag, D) into sI, 66 x 34, 2c x 3r, 396 thr ----------
    // (sI's image data is dead after stage 1; all threads synced since.)
    if (tid < 396) {
        const int rg = tid / 33, cg = tid - rg * 33;
        const int c0 = cg * 2, r0 = rg * 3;
        float acc[3][2] = {{0,0},{0,0},{0,0}};
        #pragma unroll
        for (int ir = 0; ir < 5; ir++) {
            const int rr = (r0 + ir < 36) ? r0 + ir : 35;   // sM valid rows 0..35
            const float2 v = *(const float2*)&sM[rr * STRIDE + c0];
            const float2 u = *(const float2*)&sM[rr * STRIDE + c0 + 2];
            #pragma unroll
            for (int k = 0; k < 3; k++) {
                const int ky = ir - k;
                if (ky >= 0 && ky < 3) {
                    const float d0 = cW[27+ky*3], d1 = cW[28+ky*3], d2 = cW[29+ky*3];
                    acc[k][0] = fmaf(d0, v.x, fmaf(d1, v.y, fmaf(d2, u.x, acc[k][0])));
                    acc[k][1] = fmaf(d0, v.y, fmaf(d1, u.x, fmaf(d2, u.y, acc[k][1])));
                }
            }
        }
        const float x0 = ((unsigned)(X0 - 1 + c0)     < IMG) ? 1.f : 0.f;
        const float x1 = ((unsigned)(X0 - 1 + c0 + 1) < IMG) ? 1.f : 0.f;
        #pragma unroll
        for (int k = 0; k < 3; k++) {
            const int r = r0 + k;
            if (r < 34) {
                const float ym = ((unsigned)(Y0 - 1 + r) < IMG) ? 1.f : 0.f;
                *(float2*)&sI[r * STRIDE + c0] =
                    make_float2(acc[k][0] * (x0 * ym), acc[k][1] * (x1 * ym));
            }
        }
    }
    __syncthreads();

    // ---------- stage 4: out = conv(S, R), 64 x 32, 2c x 2r, 512 threads ----------
    {
        const int rg = tid >> 5, cg = tid & 31;     // 16 rowgroups x 32 colgroups
        const int c0 = cg * 2, r0 = rg * 2;
        float acc[2][2] = {{0,0},{0,0}};
        #pragma unroll
        for (int ir = 0; ir < 4; ir++) {
            const float2 v = *(const float2*)&sI[(r0 + ir) * STRIDE + c0];
            const float2 u = *(const float2*)&sI[(r0 + ir) * STRIDE + c0 + 2];
            #pragma unroll
            for (int k = 0; k < 2; k++) {
                const int ky = ir - k;
                if (ky >= 0 && ky < 3) {
                    const float w0 = cW[36+ky*3], w1 = cW[37+ky*3], w2 = cW[38+ky*3];
                    acc[k][0] = fmaf(w0, v.x, fmaf(w1, v.y, fmaf(w2, u.x, acc[k][0])));
                    acc[k][1] = fmaf(w0, v.y, fmaf(w1, u.x, fmaf(w2, u.y, acc[k][1])));
                }
            }
        }
        #pragma unroll
        for (int k = 0; k < 2; k++)
            *(float2*)&ob[(Y0 + r0 + k) * IMG + X0 + c0] =
                make_float2(acc[k][0], acc[k][1]);
    }
}

extern "C" void kernel_launch(void* const* d_in, const int* in_sizes, int n_in,
                              void* d_out, int out_size)
{
    const float* img     = (const float*)d_in[0];
    const float* gauss_w = (const float*)d_in[1];
    const float* sobx_w  = (const float*)d_in[2];
    const float* soby_w  = (const float*)d_in[3];
    const float* dir_w   = (const float*)d_in[4];
    const float* nms_w   = (const float*)d_in[5];
    float* out = (float*)d_out;

    prep_weights<<<1, 32>>>(gauss_w, sobx_w, soby_w, dir_w, nms_w);

    void* wptr = nullptr;
    cudaGetSymbolAddress(&wptr, g_wbuf);
    cudaMemcpyToSymbolAsync(cW, wptr, 45 * sizeof(float), 0,
                            cudaMemcpyDeviceToDevice, 0);

    dim3 grid(IMG / TSX, IMG / TSY, 32);
    canny_main<<<grid, 512>>>(img, out);
}

// round 9
// speedup vs baseline: 1.4784x; 1.0329x over previous
#include <cuda_runtime.h>
#include <cuda_bf16.h>
#include <math.h>

// CannyFilter B=32,C=3,H=W=512 — unified masked 5-stage path, tile 64x32,
// 512 threads, 2 ping-pong smem buffers, 4 blocks/SM.
// sA: img tile (st0 W, st1 R) -> mag (st2 W, st3 R)
// sB: blur     (st1 W, st2 R) -> S   (st3 W, st4 R)

#define IMG 512
#define TSX 64
#define TSY 32
#define STRIDE 72      // smem row stride in floats (288B, 16B aligned)
#define SROWS 40

// cW: [0:9) G, [9:18) X, [18:27) Y, [27:36) D(sum of 8 dir), [36:45) R
__constant__ float cW[45];
__device__ float g_wbuf[45];

__global__ void prep_weights(const float* __restrict__ g, const float* __restrict__ sx,
                             const float* __restrict__ sy, const float* __restrict__ dw,
                             const float* __restrict__ nw)
{
    int t = threadIdx.x;
    if (t < 9) {
        g_wbuf[t]      = g[t];
        g_wbuf[9 + t]  = sx[t];
        g_wbuf[18 + t] = sy[t];
        float d = 0.f;
        for (int k = 0; k < 8; k++) d += dw[k * 9 + t];
        g_wbuf[27 + t] = d;
        g_wbuf[36 + t] = nw[t];
    }
}

__global__ __launch_bounds__(512, 4)
void canny_main(const float* __restrict__ img, float* __restrict__ out)
{
    __shared__ __align__(16) float sA[SROWS * STRIDE];   // img -> mag
    __shared__ __align__(16) float sB[SROWS * STRIDE];   // blur -> S

    const int tid = threadIdx.x;
    const int X0 = blockIdx.x * TSX, Y0 = blockIdx.y * TSY, b = blockIdx.z;
    const float* im = img + (size_t)b * 3 * IMG * IMG;
    float* ob = out + (size_t)b * IMG * IMG;

    // ---------- stage 0: 40x72 channel-summed img tile (float4, masked) ----------
    {
        float4* sA4 = (float4*)sA;
        #pragma unroll
        for (int it = 0; it < 2; it++) {
            const int i = tid + it * 512;
            if (i < 40 * 18) {
                const int r = i / 18, c4 = i - r * 18;
                const int gy = Y0 - 4 + r;
                const int gx = X0 - 4 + c4 * 4;          // 16B aligned
                float4 s = make_float4(0.f, 0.f, 0.f, 0.f);
                if ((unsigned)gy < IMG && (unsigned)gx < IMG) {
                    const float4* p = (const float4*)(im + gy * IMG + gx);
                    const float4 a = __ldg(p);
                    const float4 c = __ldg(p + IMG * IMG / 4);
                    const float4 d = __ldg(p + 2 * IMG * IMG / 4);
                    s = make_float4(a.x + c.x + d.x, a.y + c.y + d.y,
                                    a.z + c.z + d.z, a.w + c.w + d.w);
                }
                sA4[r * 18 + c4] = s;
            }
        }
    }
    __syncthreads();

    // ---------- stage 1: blur, 70 cols x 38 rows, 2c x 3r, 455 threads ----------
    // reads sA (img), writes sB (blur)
    if (tid < 455) {
        const int rg = tid / 35, cg = tid - rg * 35;
        const int c0 = cg * 2, r0 = rg * 3;
        float acc[3][2] = {{0,0},{0,0},{0,0}};
        #pragma unroll
        for (int ir = 0; ir < 5; ir++) {
            const int rr = (r0 + ir < SROWS) ? r0 + ir : SROWS - 1;
            const float2 v = *(const float2*)&sA[rr * STRIDE + c0];
            const float2 u = *(const float2*)&sA[rr * STRIDE + c0 + 2];
            #pragma unroll
            for (int k = 0; k < 3; k++) {
                const int ky = ir - k;
                if (ky >= 0 && ky < 3) {
                    const float g0 = cW[ky*3], g1 = cW[ky*3+1], g2 = cW[ky*3+2];
                    acc[k][0] = fmaf(g0, v.x, fmaf(g1, v.y, fmaf(g2, u.x, acc[k][0])));
                    acc[k][1] = fmaf(g0, v.y, fmaf(g1, u.x, fmaf(g2, u.y, acc[k][1])));
                }
            }
        }
        const float x0 = ((unsigned)(X0 - 3 + c0)     < IMG) ? 1.f : 0.f;
        const float x1 = ((unsigned)(X0 - 3 + c0 + 1) < IMG) ? 1.f : 0.f;
        #pragma unroll
        for (int k = 0; k < 3; k++) {
            const int r = r0 + k;
            if (r < 38) {
                const float ym = ((unsigned)(Y0 - 3 + r) < IMG) ? 1.f : 0.f;
                *(float2*)&sB[r * STRIDE + c0] =
                    make_float2(acc[k][0] * (x0 * ym), acc[k][1] * (x1 * ym));
            }
        }
    }
    __syncthreads();

    // ---------- stage 2: sobel-mag, 68 cols x 36 rows, 2c x 3r, 408 threads ----------
    // reads sB (blur), writes sA (mag; img data dead)
    if (tid < 408) {
        const int rg = tid / 34, cg = tid - rg * 34;
        const int c0 = cg * 2, r0 = rg * 3;
        float ax[3][2] = {{0,0},{0,0},{0,0}}, ay[3][2] = {{0,0},{0,0},{0,0}};
        #pragma unroll
        for (int ir = 0; ir < 5; ir++) {
            const float2 v = *(const float2*)&sB[(r0 + ir) * STRIDE + c0];
            const float2 u = *(const float2*)&sB[(r0 + ir) * STRIDE + c0 + 2];
            #pragma unroll
            for (int k = 0; k < 3; k++) {
                const int ky = ir - k;
                if (ky >= 0 && ky < 3) {
                    const float sx0 = cW[9+ky*3], sx1 = cW[10+ky*3], sx2 = cW[11+ky*3];
                    const float sy0 = cW[18+ky*3], sy1 = cW[19+ky*3], sy2 = cW[20+ky*3];
                    ax[k][0] = fmaf(sx0, v.x, fmaf(sx1, v.y, fmaf(sx2, u.x, ax[k][0])));
                    ax[k][1] = fmaf(sx0, v.y, fmaf(sx1, u.x, fmaf(sx2, u.y, ax[k][1])));
                    ay[k][0] = fmaf(sy0, v.x, fmaf(sy1, v.y, fmaf(sy2, u.x, ay[k][0])));
                    ay[k][1] = fmaf(sy0, v.y, fmaf(sy1, u.x, fmaf(sy2, u.y, ay[k][1])));
                }
            }
        }
        const float x0 = ((unsigned)(X0 - 2 + c0)     < IMG) ? 1.f : 0.f;
        const float x1 = ((unsigned)(X0 - 2 + c0 + 1) < IMG) ? 1.f : 0.f;
        #pragma unroll
        for (int k = 0; k < 3; k++) {
            const int r = r0 + k;
            const float ym = ((unsigned)(Y0 - 2 + r) < IMG) ? 1.f : 0.f;
            const float m0 = sqrtf(ax[k][0]*ax[k][0] + ay[k][0]*ay[k][0]) * (1.f/3.f);
            const float m1 = sqrtf(ax[k][1]*ax[k][1] + ay[k][1]*ay[k][1]) * (1.f/3.f);
            *(float2*)&sA[r * STRIDE + c0] = make_float2(m0 * (x0 * ym), m1 * (x1 * ym));
        }
    }
    __syncthreads();

    // ---------- stage 3: S = conv(mag, D), 66 x 34, 2c x 3r, 396 threads ----------
    // reads sA (mag), writes sB (S; blur data dead)
    if (tid < 396) {
        const int rg = tid / 33, cg = tid - rg * 33;
        const int c0 = cg * 2, r0 = rg * 3;
        float acc[3][2] = {{0,0},{0,0},{0,0}};
        #pragma unroll
        for (int ir = 0; ir < 5; ir++) {
            const int rr = (r0 + ir < 36) ? r0 + ir : 35;   // mag valid rows 0..35
            const float2 v = *(const float2*)&sA[rr * STRIDE + c0];
            const float2 u = *(const float2*)&sA[rr * STRIDE + c0 + 2];
            #pragma unroll
            for (int k = 0; k < 3; k++) {
                const int ky = ir - k;
                if (ky >= 0 && ky < 3) {
                    const float d0 = cW[27+ky*3], d1 = cW[28+ky*3], d2 = cW[29+ky*3];
                    acc[k][0] = fmaf(d0, v.x, fmaf(d1, v.y, fmaf(d2, u.x, acc[k][0])));
                    acc[k][1] = fmaf(d0, v.y, fmaf(d1, u.x, fmaf(d2, u.y, acc[k][1])));
                }
            }
        }
        const float x0 = ((unsigned)(X0 - 1 + c0)     < IMG) ? 1.f : 0.f;
        const float x1 = ((unsigned)(X0 - 1 + c0 + 1) < IMG) ? 1.f : 0.f;
        #pragma unroll
        for (int k = 0; k < 3; k++) {
            const int r = r0 + k;
            if (r < 34) {
                const float ym = ((unsigned)(Y0 - 1 + r) < IMG) ? 1.f : 0.f;
                *(float2*)&sB[r * STRIDE + c0] =
                    make_float2(acc[k][0] * (x0 * ym), acc[k][1] * (x1 * ym));
            }
        }
    }
    __syncthreads();

    // ---------- stage 4: out = conv(S, R), 64 x 32, 4c x 1r, 512 threads ----------
    // reads sB (S rows 0..33, cols 0..65), writes gmem via STG.128
    {
        const int rg = tid >> 4, cg = tid & 15;     // 32 rows x 16 colgroups
        const int c0 = cg * 4, r0 = rg;
        float acc[4] = {0, 0, 0, 0};
        #pragma unroll
        for (int ir = 0; ir < 3; ir++) {
            const float4 v4 = *(const float4*)&sB[(r0 + ir) * STRIDE + c0];
            const float2 u2 = *(const float2*)&sB[(r0 + ir) * STRIDE + c0 + 4];
            const float v[6] = {v4.x, v4.y, v4.z, v4.w, u2.x, u2.y};
            const float w0 = cW[36+ir*3], w1 = cW[37+ir*3], w2 = cW[38+ir*3];
            #pragma unroll
            for (int j = 0; j < 4; j++)
                acc[j] = fmaf(w0, v[j], fmaf(w1, v[j+1], fmaf(w2, v[j+2], acc[j])));
        }
        *(float4*)&ob[(Y0 + r0) * IMG + X0 + c0] =
            make_float4(acc[0], acc[1], acc[2], acc[3]);
    }
}

extern "C" void kernel_launch(void* const* d_in, const int* in_sizes, int n_in,
                              void* d_out, int out_size)
{
    const float* img     = (const float*)d_in[0];
    const float* gauss_w = (const float*)d_in[1];
    const float* sobx_w  = (const float*)d_in[2];
    const float* soby_w  = (const float*)d_in[3];
    const float* dir_w   = (const float*)d_in[4];
    const float* nms_w   = (const float*)d_in[5];
    float* out = (float*)d_out;

    prep_weights<<<1, 32>>>(gauss_w, sobx_w, soby_w, dir_w, nms_w);

    void* wptr = nullptr;
    cudaGetSymbolAddress(&wptr, g_wbuf);
    cudaMemcpyToSymbolAsync(cW, wptr, 45 * sizeof(float), 0,
                            cudaMemcpyDeviceToDevice, 0);

    dim3 grid(IMG / TSX, IMG / TSY, 32);
    canny_main<<<grid, 512>>>(img, out);
}

// round 10
// speedup vs baseline: 1.4844x; 1.0041x over previous
#include <cuda_runtime.h>
#include <cuda_bf16.h>
#include <math.h>

// CannyFilter B=32,C=3,H=W=512 — unified masked 5-stage path, tile 128x32,
// 512 threads, 2 ping-pong smem buffers, 4col x 3row register strips.
// sA: img tile (st0 W, st1 R) -> mag (st2 W, st3 R)
// sB: blur     (st1 W, st2 R) -> S   (st3 W, st4 R)

#define IMG 512
#define TSX 128
#define TSY 32
#define STRIDE 140     // smem row stride in floats (560B, 16B aligned)
#define SROWS 40

// cW: [0:9) G, [9:18) X, [18:27) Y, [27:36) D(sum of 8 dir), [36:45) R
__constant__ float cW[45];
__device__ float g_wbuf[45];

__global__ void prep_weights(const float* __restrict__ g, const float* __restrict__ sx,
                             const float* __restrict__ sy, const float* __restrict__ dw,
                             const float* __restrict__ nw)
{
    int t = threadIdx.x;
    if (t < 9) {
        g_wbuf[t]      = g[t];
        g_wbuf[9 + t]  = sx[t];
        g_wbuf[18 + t] = sy[t];
        float d = 0.f;
        for (int k = 0; k < 8; k++) d += dw[k * 9 + t];
        g_wbuf[27 + t] = d;
        g_wbuf[36 + t] = nw[t];
    }
}

__global__ __launch_bounds__(512, 3)
void canny_main(const float* __restrict__ img, float* __restrict__ out)
{
    __shared__ __align__(16) float sA[SROWS * STRIDE];   // img -> mag
    __shared__ __align__(16) float sB[SROWS * STRIDE];   // blur -> S

    const int tid = threadIdx.x;
    const int X0 = blockIdx.x * TSX, Y0 = blockIdx.y * TSY, b = blockIdx.z;
    const float* im = img + (size_t)b * 3 * IMG * IMG;
    float* ob = out + (size_t)b * IMG * IMG;

    // ---------- stage 0: 40 x 136 channel-summed img tile (float4, masked) ----------
    // 34 float4 per row x 40 rows = 1360 vectors.
    for (int i = tid; i < 40 * 34; i += 512) {
        const int r = i / 34, c4 = i - r * 34;
        const int gy = Y0 - 4 + r;
        const int gx = X0 - 4 + c4 * 4;              // 16B aligned; fully in or out
        float4 s = make_float4(0.f, 0.f, 0.f, 0.f);
        if ((unsigned)gy < IMG && (unsigned)gx < IMG) {
            const float4* p = (const float4*)(im + gy * IMG + gx);
            const float4 a = __ldg(p);
            const float4 c = __ldg(p + IMG * IMG / 4);
            const float4 d = __ldg(p + 2 * IMG * IMG / 4);
            s = make_float4(a.x + c.x + d.x, a.y + c.y + d.y,
                            a.z + c.z + d.z, a.w + c.w + d.w);
        }
        *(float4*)&sA[r * STRIDE + c4 * 4] = s;
    }
    __syncthreads();

    // ---------- stage 1: blur, 134 cols x 38 rows, 4c x 3r, 442 threads ----------
    // reads sA (img), writes sB (blur). cols 134,135 of sB get garbage (never read).
    if (tid < 442) {
        const int rg = tid / 34, cg = tid - rg * 34;
        const int c0 = cg * 4, r0 = rg * 3;
        float acc[3][4] = {{0,0,0,0},{0,0,0,0},{0,0,0,0}};
        #pragma unroll
        for (int ir = 0; ir < 5; ir++) {
            const int rr = (r0 + ir < SROWS) ? r0 + ir : SROWS - 1;
            const float4 a = *(const float4*)&sA[rr * STRIDE + c0];
            const float2 e = *(const float2*)&sA[rr * STRIDE + c0 + 4];
            const float v[6] = {a.x, a.y, a.z, a.w, e.x, e.y};
            #pragma unroll
            for (int k = 0; k < 3; k++) {
                const int ky = ir - k;
                if (ky >= 0 && ky < 3) {
                    const float g0 = cW[ky*3], g1 = cW[ky*3+1], g2 = cW[ky*3+2];
                    #pragma unroll
                    for (int j = 0; j < 4; j++)
                        acc[k][j] = fmaf(g0, v[j], fmaf(g1, v[j+1],
                                         fmaf(g2, v[j+2], acc[k][j])));
                }
            }
        }
        float xm[4];
        #pragma unroll
        for (int j = 0; j < 4; j++)
            xm[j] = ((unsigned)(X0 - 3 + c0 + j) < IMG) ? 1.f : 0.f;
        #pragma unroll
        for (int k = 0; k < 3; k++) {
            const int r = r0 + k;
            if (r < 38) {
                const float ym = ((unsigned)(Y0 - 3 + r) < IMG) ? 1.f : 0.f;
                *(float4*)&sB[r * STRIDE + c0] =
                    make_float4(acc[k][0] * (xm[0] * ym), acc[k][1] * (xm[1] * ym),
                                acc[k][2] * (xm[2] * ym), acc[k][3] * (xm[3] * ym));
            }
        }
    }
    __syncthreads();

    // ---------- stage 2: sobel-mag, 132 cols x 36 rows, 4c x 3r, 396 threads ----------
    // reads sB (blur, cols<=133 all valid), writes sA (mag; img dead)
    if (tid < 396) {
        const int rg = tid / 33, cg = tid - rg * 33;
        const int c0 = cg * 4, r0 = rg * 3;
        float ax[3][4] = {{0,0,0,0},{0,0,0,0},{0,0,0,0}};
        float ay[3][4] = {{0,0,0,0},{0,0,0,0},{0,0,0,0}};
        #pragma unroll
        for (int ir = 0; ir < 5; ir++) {
            const float4 a = *(const float4*)&sB[(r0 + ir) * STRIDE + c0];
            const float2 e = *(const float2*)&sB[(r0 + ir) * STRIDE + c0 + 4];
            const float v[6] = {a.x, a.y, a.z, a.w, e.x, e.y};
            #pragma unroll
            for (int k = 0; k < 3; k++) {
                const int ky = ir - k;
                if (ky >= 0 && ky < 3) {
                    const float sx0 = cW[9+ky*3], sx1 = cW[10+ky*3], sx2 = cW[11+ky*3];
                    const float sy0 = cW[18+ky*3], sy1 = cW[19+ky*3], sy2 = cW[20+ky*3];
                    #pragma unroll
                    for (int j = 0; j < 4; j++) {
                        ax[k][j] = fmaf(sx0, v[j], fmaf(sx1, v[j+1],
                                        fmaf(sx2, v[j+2], ax[k][j])));
                        ay[k][j] = fmaf(sy0, v[j], fmaf(sy1, v[j+1],
                                        fmaf(sy2, v[j+2], ay[k][j])));
                    }
                }
            }
        }
        float xm[4];
        #pragma unroll
        for (int j = 0; j < 4; j++)
            xm[j] = ((unsigned)(X0 - 2 + c0 + j) < IMG) ? 1.f : 0.f;
        #pragma unroll
        for (int k = 0; k < 3; k++) {
            const int r = r0 + k;
            const float ym = ((unsigned)(Y0 - 2 + r) < IMG) ? 1.f : 0.f;
            float m[4];
            #pragma unroll
            for (int j = 0; j < 4; j++)
                m[j] = sqrtf(ax[k][j]*ax[k][j] + ay[k][j]*ay[k][j]) * (1.f/3.f)
                       * (xm[j] * ym);
            *(float4*)&sA[r * STRIDE + c0] = make_float4(m[0], m[1], m[2], m[3]);
        }
    }
    __syncthreads();

    // ---------- stage 3: S = conv(mag, D), 130(+2) cols x 34 rows, 4c x 3r ----------
    // reads sA (mag rows<=35 valid via clamp; cols 132,133 garbage only feed
    // S cols 130,131 which are never read), writes sB (S; blur dead)
    if (tid < 396) {
        const int rg = tid / 33, cg = tid - rg * 33;
        const int c0 = cg * 4, r0 = rg * 3;
        float acc[3][4] = {{0,0,0,0},{0,0,0,0},{0,0,0,0}};
        #pragma unroll
        for (int ir = 0; ir < 5; ir++) {
            const int rr = (r0 + ir < 36) ? r0 + ir : 35;
            const float4 a = *(const float4*)&sA[rr * STRIDE + c0];
            const float2 e = *(const float2*)&sA[rr * STRIDE + c0 + 4];
            const float v[6] = {a.x, a.y, a.z, a.w, e.x, e.y};
            #pragma unroll
            for (int k = 0; k < 3; k++) {
                const int ky = ir - k;
                if (ky >= 0 && ky < 3) {
                    const float d0 = cW[27+ky*3], d1 = cW[28+ky*3], d2 = cW[29+ky*3];
                    #pragma unroll
                    for (int j = 0; j < 4; j++)
                        acc[k][j] = fmaf(d0, v[j], fmaf(d1, v[j+1],
                                         fmaf(d2, v[j+2], acc[k][j])));
                }
            }
        }
        float xm[4];
        #pragma unroll
        for (int j = 0; j < 4; j++)
            xm[j] = ((unsigned)(X0 - 1 + c0 + j) < IMG) ? 1.f : 0.f;
        #pragma unroll
        for (int k = 0; k < 3; k++) {
            const int r = r0 + k;
            if (r < 34) {
                const float ym = ((unsigned)(Y0 - 1 + r) < IMG) ? 1.f : 0.f;
                *(float4*)&sB[r * STRIDE + c0] =
                    make_float4(acc[k][0] * (xm[0] * ym), acc[k][1] * (xm[1] * ym),
                                acc[k][2] * (xm[2] * ym), acc[k][3] * (xm[3] * ym));
            }
        }
    }
    __syncthreads();

    // ---------- stage 4: out = conv(S, R), 128 x 32, 4c x 2r, 512 threads ----------
    // reads sB (S rows 0..33, cols 0..129 all valid), writes gmem via STG.128
    {
        const int rg = tid >> 5, cg = tid & 31;     // 16 rowgroups x 32 colgroups
        const int c0 = cg * 4, r0 = rg * 2;
        float acc[2][4] = {{0,0,0,0},{0,0,0,0}};
        #pragma unroll
        for (int ir = 0; ir < 4; ir++) {
            const float4 a = *(const float4*)&sB[(r0 + ir) * STRIDE + c0];
            const float2 e = *(const float2*)&sB[(r0 + ir) * STRIDE + c0 + 4];
            const float v[6] = {a.x, a.y, a.z, a.w, e.x, e.y};
            #pragma unroll
            for (int k = 0; k < 2; k++) {
                const int ky = ir - k;
                if (ky >= 0 && ky < 3) {
                    const float w0 = cW[36+ky*3], w1 = cW[37+ky*3], w2 = cW[38+ky*3];
                    #pragma unroll
                    for (int j = 0; j < 4; j++)
                        acc[k][j] = fmaf(w0, v[j], fmaf(w1, v[j+1],
                                         fmaf(w2, v[j+2], acc[k][j])));
                }
            }
        }
        #pragma unroll
        for (int k = 0; k < 2; k++)
            *(float4*)&ob[(Y0 + r0 + k) * IMG + X0 + c0] =
                make_float4(acc[k][0], acc[k][1], acc[k][2], acc[k][3]);
    }
}

extern "C" void kernel_launch(void* const* d_in, const int* in_sizes, int n_in,
                              void* d_out, int out_size)
{
    const float* img     = (const float*)d_in[0];
    const float* gauss_w = (const float*)d_in[1];
    const float* sobx_w  = (const float*)d_in[2];
    const float* soby_w  = (const float*)d_in[3];
    const float* dir_w   = (const float*)d_in[4];
    const float* nms_w   = (const float*)d_in[5];
    float* out = (float*)d_out;

    prep_weights<<<1, 32>>>(gauss_w, sobx_w, soby_w, dir_w, nms_w);

    void* wptr = nullptr;
    cudaGetSymbolAddress(&wptr, g_wbuf);
    cudaMemcpyToSymbolAsync(cW, wptr, 45 * sizeof(float), 0,
                            cudaMemcpyDeviceToDevice, 0);

    dim3 grid(IMG / TSX, IMG / TSY, 32);
    canny_main<<<grid, 512>>>(img, out);
}